// round 5
// baseline (speedup 1.0000x reference)
#include <cuda_runtime.h>
#include <cuda_bf16.h>
#include <cstdint>

#define BB 512
#define DD 256
#define S_SCALE 30.0f
#define MARGIN 0.2f
#define EXPC 43.2808512f   // 30 * log2(e)

// -------- device scratch --------
__device__ __nv_bfloat16 g_xn[BB * DD];     // normalized X, bf16
__device__ float g_sumexp[BB];
__device__ float g_cost[BB];
__device__ int   g_targets[BB];

// ---------------- helpers ----------------
__device__ __forceinline__ uint32_t smem_u32(const void* p) {
    uint32_t a;
    asm("{ .reg .u64 t; cvta.to.shared.u64 t, %1; cvt.u32.u64 %0, t; }"
        : "=r"(a) : "l"(p));
    return a;
}

#define CP16F(sa, ga) \
    asm volatile("cp.async.cg.shared.global [%0], [%1], 16;" \
                 :: "r"(sa), "l"(ga) : "memory")
#define CP_COMMIT() asm volatile("cp.async.commit_group;" ::: "memory")
#define CP_WAIT1()  asm volatile("cp.async.wait_group 1;" ::: "memory")
#define CP_WAIT0()  asm volatile("cp.async.wait_group 0;" ::: "memory")

#define LDSM4(r0, r1, r2, r3, addr) \
    asm volatile("ldmatrix.sync.aligned.m8n8.x4.shared.b16 {%0,%1,%2,%3}, [%4];" \
                 : "=r"(r0), "=r"(r1), "=r"(r2), "=r"(r3) : "r"(addr))

__device__ __forceinline__ void mma16816(float* d, const uint32_t* a,
                                         uint32_t b0, uint32_t b1) {
    asm volatile(
        "mma.sync.aligned.m16n8k16.row.col.f32.bf16.bf16.f32 "
        "{%0,%1,%2,%3}, {%4,%5,%6,%7}, {%8,%9}, {%0,%1,%2,%3};\n"
        : "+f"(d[0]), "+f"(d[1]), "+f"(d[2]), "+f"(d[3])
        : "r"(a[0]), "r"(a[1]), "r"(a[2]), "r"(a[3]), "r"(b0), "r"(b1));
}

__device__ __forceinline__ uint32_t pack_bf2(float x, float y) {
    __nv_bfloat162 h = __floats2bfloat162_rn(x, y);
    return *reinterpret_cast<uint32_t*>(&h);
}
__device__ __forceinline__ float2 bf2_to_f2(unsigned u) {
    __nv_bfloat162 h;
    *reinterpret_cast<unsigned*>(&h) = u;
    return __bfloat1622float2(h);
}

// SW128 blocked-atom tile: 128 rows x 256 bf16 (32 chunks of 16B per row).
__device__ __forceinline__ uint32_t tile_off(int r, int cc) {
    return (uint32_t)(((r >> 3) + (cc >> 3) * 16) * 1024
                    + (r & 7) * 128 + ((((cc & 7) * 16) ^ ((r & 7) << 4))));
}

// ---------------------------------------------------------
// prep + X normalize (merged).
// grid 64 x 256: every block normalizes 8 X rows; block 0 also decodes
// targets (int64 vs int32) and zeros g_sumexp.
__global__ void prep_norm_kernel(const float* __restrict__ in,
                                 const int* __restrict__ t32) {
    if (blockIdx.x == 0) {
        __shared__ int flag;
        int i = threadIdx.x;  // 256 threads
        if (i == 0) flag = 0;
        __syncthreads();
        if (t32[2 * i + 1] != 0) flag = 1;   // odd words of first 512
        __syncthreads();
#pragma unroll
        for (int k = 0; k < 2; k++) {
            int j = i + 256 * k;
            g_targets[j] = flag ? t32[j] : (int)((const long long*)t32)[j];
            g_sumexp[j] = 0.0f;
        }
    }
    int row = blockIdx.x * 8 + (threadIdx.x >> 5);
    int lane = threadIdx.x & 31;
    const float4* p = (const float4*)(in + (size_t)row * DD);
    float4 v0 = p[lane];
    float4 v1 = p[lane + 32];
    float s = v0.x * v0.x + v0.y * v0.y + v0.z * v0.z + v0.w * v0.w
            + v1.x * v1.x + v1.y * v1.y + v1.z * v1.z + v1.w * v1.w;
#pragma unroll
    for (int o = 16; o; o >>= 1) s += __shfl_xor_sync(0xffffffffu, s, o);
    float inv = rsqrtf(s);
    unsigned* q = (unsigned*)(g_xn + (size_t)row * DD);
    q[2 * lane + 0]        = pack_bf2(v0.x * inv, v0.y * inv);
    q[2 * lane + 1]        = pack_bf2(v0.z * inv, v0.w * inv);
    q[2 * (lane + 32) + 0] = pack_bf2(v1.x * inv, v1.y * inv);
    q[2 * (lane + 32) + 1] = pack_bf2(v1.z * inv, v1.w * inv);
}

// ---------------------------------------------------------
// target cosine from fp32 W (normalize + round through bf16 = GEMM numerics)
__global__ void cost_kernel(const float* __restrict__ W) {
    int b = blockIdx.x * 8 + (threadIdx.x >> 5);
    int lane = threadIdx.x & 31;
    int c = g_targets[b];
    const float4* wr = (const float4*)(W + (size_t)c * DD);
    float4 a = wr[lane];
    float4 d = wr[lane + 32];
    float ss = a.x * a.x + a.y * a.y + a.z * a.z + a.w * a.w
             + d.x * d.x + d.y * d.y + d.z * d.z + d.w * d.w;
#pragma unroll
    for (int o = 16; o; o >>= 1) ss += __shfl_xor_sync(0xffffffffu, ss, o);
    float inv = rsqrtf(ss);

    const unsigned* xr = (const unsigned*)(g_xn + (size_t)b * DD);
    float s = 0.0f;
    {
        float2 w01 = bf2_to_f2(pack_bf2(a.x * inv, a.y * inv));
        float2 w23 = bf2_to_f2(pack_bf2(a.z * inv, a.w * inv));
        float2 x01 = bf2_to_f2(xr[2 * lane]);
        float2 x23 = bf2_to_f2(xr[2 * lane + 1]);
        s += w01.x * x01.x + w01.y * x01.y + w23.x * x23.x + w23.y * x23.y;
    }
    {
        float2 w01 = bf2_to_f2(pack_bf2(d.x * inv, d.y * inv));
        float2 w23 = bf2_to_f2(pack_bf2(d.z * inv, d.w * inv));
        float2 x01 = bf2_to_f2(xr[2 * (lane + 32)]);
        float2 x23 = bf2_to_f2(xr[2 * (lane + 32) + 1]);
        s += w01.x * x01.x + w01.y * x01.y + w23.x * x23.x + w23.y * x23.y;
    }
#pragma unroll
    for (int o = 16; o; o >>= 1) s += __shfl_xor_sync(0xffffffffu, s, o);
    if (lane == 0) g_cost[b] = s;
}

// ---------------------------------------------------------
// GEMM + exp-sum with fused W normalization.
// CTA: 128-class tile. W fp32 read once (2-pass: sumsq, then L1-hit re-read ->
// bf16 SW128 tile). X bf16 double-buffered via cp.async. mma.sync m16n8k16.
#define SM_W   0
#define SM_X0  65536
#define SM_X1  131072
#define SM_TOTAL 196608

__global__ __launch_bounds__(256, 1) void gemm_sumexp_kernel(
        const float* __restrict__ W, int C) {
    extern __shared__ char smem[];
    const uint32_t sb = smem_u32(smem);
    const int tid = threadIdx.x, wid = tid >> 5, lane = tid & 31;
    const int cbase = blockIdx.x * 128;
    const char* xsrc = (const char*)g_xn;

    // prefetch X blocks 0,1 (async)
#pragma unroll
    for (int it = 0; it < 16; it++) {
        int i = tid + 256 * it, r = i >> 5, cc = i & 31;
        CP16F(sb + SM_X0 + tile_off(r, cc), xsrc + ((size_t)r * 32 + cc) * 16);
    }
    CP_COMMIT();
#pragma unroll
    for (int it = 0; it < 16; it++) {
        int i = tid + 256 * it, r = i >> 5, cc = i & 31;
        CP16F(sb + SM_X1 + tile_off(r, cc), xsrc + ((size_t)(128 + r) * 32 + cc) * 16);
    }
    CP_COMMIT();

    // fused W normalization: 2 threads per row (halves), 2-pass
    {
        int r = tid >> 1, h = tid & 1;
        int cg = cbase + r;
        bool ok = (cg < C);
        const float4* wrow =
            (const float4*)(W + (size_t)(ok ? cg : cbase) * DD) + h * 32;
        float ss = 0.f;
#pragma unroll
        for (int i = 0; i < 32; i++) {
            float4 v = wrow[i];
            ss += v.x * v.x + v.y * v.y + v.z * v.z + v.w * v.w;
        }
        ss += __shfl_xor_sync(0xffffffffu, ss, 1);
        float inv = ok ? rsqrtf(ss) : 0.f;
#pragma unroll
        for (int i = 0; i < 16; i++) {
            float4 a = wrow[2 * i];        // L1 hit
            float4 d = wrow[2 * i + 1];
            uint4 u;
            u.x = pack_bf2(a.x * inv, a.y * inv);
            u.y = pack_bf2(a.z * inv, a.w * inv);
            u.z = pack_bf2(d.x * inv, d.y * inv);
            u.w = pack_bf2(d.z * inv, d.w * inv);
            *(uint4*)(smem + SM_W + tile_off(r, h * 16 + i)) = u;
        }
    }
    CP_WAIT1();        // X0 resident; X1 in flight
    __syncthreads();

    const int wm = wid & 3, wn = wid >> 2;
    const int m0 = wm * 32, n0 = wn * 64;
    const int a_rl   = ((lane >> 3) & 1) * 8 + (lane & 7);
    const int a_cchi = (lane >> 4) & 1;
    const int b_rl   = ((lane >> 4) & 1) * 8 + (lane & 7);
    const int b_cchi = (lane >> 3) & 1;

    for (int b = 0; b < 4; b++) {
        const uint32_t xa = sb + ((b & 1) ? SM_X1 : SM_X0);
        const uint32_t wa = sb + SM_W;

        float acc[2][8][4];
#pragma unroll
        for (int i = 0; i < 2; i++)
#pragma unroll
            for (int j = 0; j < 8; j++)
#pragma unroll
                for (int q = 0; q < 4; q++) acc[i][j][q] = 0.0f;

#pragma unroll
        for (int s = 0; s < 16; s++) {
            uint32_t afr[2][4];
#pragma unroll
            for (int i = 0; i < 2; i++) {
                int r = m0 + 16 * i + a_rl, cc = 2 * s + a_cchi;
                LDSM4(afr[i][0], afr[i][1], afr[i][2], afr[i][3],
                      xa + tile_off(r, cc));
            }
            uint32_t bfr[4][4];
#pragma unroll
            for (int j4 = 0; j4 < 4; j4++) {
                int r = n0 + 16 * j4 + b_rl, cc = 2 * s + b_cchi;
                LDSM4(bfr[j4][0], bfr[j4][1], bfr[j4][2], bfr[j4][3],
                      wa + tile_off(r, cc));
            }
#pragma unroll
            for (int j = 0; j < 8; j++) {
                uint32_t b0 = bfr[j >> 1][(j & 1) * 2];
                uint32_t b1 = bfr[j >> 1][(j & 1) * 2 + 1];
                mma16816(acc[0][j], afr[0], b0, b1);
                mma16816(acc[1][j], afr[1], b0, b1);
            }
        }

        // epilogue: exp2-based exp + per-row reduce
        float rs[4] = {0.f, 0.f, 0.f, 0.f};
#pragma unroll
        for (int i = 0; i < 2; i++)
#pragma unroll
            for (int j = 0; j < 8; j++) {
                rs[2 * i]     += exp2f(fmaf(EXPC, acc[i][j][0], -EXPC))
                               + exp2f(fmaf(EXPC, acc[i][j][1], -EXPC));
                rs[2 * i + 1] += exp2f(fmaf(EXPC, acc[i][j][2], -EXPC))
                               + exp2f(fmaf(EXPC, acc[i][j][3], -EXPC));
            }
#pragma unroll
        for (int q = 0; q < 4; q++) {
            rs[q] += __shfl_xor_sync(0xffffffffu, rs[q], 1);
            rs[q] += __shfl_xor_sync(0xffffffffu, rs[q], 2);
        }
        if ((lane & 3) == 0) {
            int rbase = b * 128 + m0 + (lane >> 2);
#pragma unroll
            for (int q = 0; q < 4; q++)
                atomicAdd(&g_sumexp[rbase + 8 * q], rs[q]);
        }

        __syncthreads();   // everyone done reading buf[b&1]
        if (b < 2) {
            uint32_t dst = sb + ((b & 1) ? SM_X1 : SM_X0);
#pragma unroll
            for (int it = 0; it < 16; it++) {
                int i = tid + 256 * it, r = i >> 5, cc = i & 31;
                CP16F(dst + tile_off(r, cc),
                      xsrc + ((size_t)((b + 2) * 128 + r) * 32 + cc) * 16);
            }
            CP_COMMIT();
            CP_WAIT1();
        } else if (b == 2) {
            CP_WAIT0();
        }
        __syncthreads();
    }
}

// ---------------------------------------------------------
// finalize: pad correction, margin correction, lse, mean
__global__ void finalize_kernel(float* __restrict__ out, int npad) {
    __shared__ double sd[BB];
    int b = threadIdx.x;
    float ct = g_cost[b];
    float lt = S_SCALE * (ct - MARGIN);
    float s = g_sumexp[b] - (float)npad * expf(-30.0f)
            + __expf(lt - 30.0f) - exp2f(fmaf(EXPC, ct, -EXPC));
    float nll = 30.0f + logf(s) - lt;
    sd[b] = (double)nll;
    __syncthreads();
    for (int o = 256; o; o >>= 1) {
        if (b < o) sd[b] += sd[b + o];
        __syncthreads();
    }
    if (b == 0) out[0] = (float)(sd[0] / (double)BB);
}

// ---------------------------------------------------------
extern "C" void kernel_launch(void* const* d_in, const int* in_sizes, int n_in,
                              void* d_out, int out_size) {
    const float* inputs  = (const float*)d_in[0];
    const float* weight  = (const float*)d_in[1];
    const int*   targets = (const int*)d_in[2];
    float* out = (float*)d_out;

    int C = in_sizes[1] / DD;
    int gridC = (C + 127) / 128;
    int npad = gridC * 128 - C;

    cudaFuncSetAttribute(gemm_sumexp_kernel,
                         cudaFuncAttributeMaxDynamicSharedMemorySize, SM_TOTAL);

    prep_norm_kernel<<<BB / 8, 256>>>(inputs, targets);
    cost_kernel<<<BB / 8, 256>>>(weight);
    gemm_sumexp_kernel<<<gridC, 256, SM_TOTAL>>>(weight, C);
    finalize_kernel<<<1, BB>>>(out, npad);
}